// round 2
// baseline (speedup 1.0000x reference)
#include <cuda_runtime.h>
#include <math.h>

#define BATCH 4
#define NPTS  8192
#define TPB   256
#define PPT   4                         // query points per thread
#define PPB   (TPB * PPT)               // 1024 query points per block
#define PCHUNKS (NPTS / PPB)            // 8
#define CHUNK 1024                      // "other" points staged in smem
#define OCHUNKS (NPTS / CHUNK)          // 8
#define TOTAL_MIN (2 * BATCH * NPTS)    // 65536 min slots (both directions)
#define RBLOCKS 64

__device__ unsigned g_min[TOTAL_MIN];
__device__ float    g_part[RBLOCKS];

__global__ void init_kernel() {
    int i = blockIdx.x * blockDim.x + threadIdx.x;
    if (i < TOTAL_MIN) g_min[i] = 0x7f800000u;  // +inf
}

__global__ void __launch_bounds__(TPB) chamfer_main(
    const float* __restrict__ pred, const float* __restrict__ gt)
{
    __shared__ float sx[CHUNK], sy[CHUNK], sz[CHUNK];

    int bid = blockIdx.x;
    int oc   = bid % OCHUNKS;  bid /= OCHUNKS;
    int pcid = bid % PCHUNKS;  bid /= PCHUNKS;
    int b    = bid % BATCH;    bid /= BATCH;
    int dir  = bid;  // 0: query=pred scan=gt ; 1: query=gt scan=pred

    const float* Aq = (dir == 0 ? pred : gt) + (size_t)b * 3 * NPTS;
    const float* Bs = (dir == 0 ? gt : pred) + (size_t)b * 3 * NPTS;

    // Stage one chunk of the scanned cloud into smem (coalesced: [3,N] layout)
    int jbase = oc * CHUNK;
    for (int idx = threadIdx.x; idx < CHUNK; idx += TPB) {
        sx[idx] = Bs[jbase + idx];
        sy[idx] = Bs[NPTS + jbase + idx];
        sz[idx] = Bs[2 * NPTS + jbase + idx];
    }
    __syncthreads();

    float px[PPT], py[PPT], pz[PPT], mn[PPT];
    int i0 = pcid * PPB + threadIdx.x;
    #pragma unroll
    for (int p = 0; p < PPT; p++) {
        int i = i0 + p * TPB;
        px[p] = Aq[i];
        py[p] = Aq[NPTS + i];
        pz[p] = Aq[2 * NPTS + i];
        mn[p] = 3.0e38f;
    }

    #pragma unroll 4
    for (int j = 0; j < CHUNK; j++) {
        float gx = sx[j], gy = sy[j], gz = sz[j];  // LDS broadcast
        #pragma unroll
        for (int p = 0; p < PPT; p++) {
            float dx = px[p] - gx;
            float dy = py[p] - gy;
            float dz = pz[p] - gz;
            float d2 = fmaf(dx, dx, fmaf(dy, dy, dz * dz));
            mn[p] = fminf(mn[p], d2);
        }
    }

    unsigned* gm = g_min + (size_t)dir * BATCH * NPTS + (size_t)b * NPTS;
    #pragma unroll
    for (int p = 0; p < PPT; p++) {
        // nonnegative floats: uint order == float order -> exact deterministic min
        atomicMin(&gm[i0 + p * TPB], __float_as_uint(mn[p]));
    }
}

__global__ void __launch_bounds__(256) reduce_kernel() {
    __shared__ float ssum[256];
    int tid = threadIdx.x;
    float s = 0.0f;
    for (int i = blockIdx.x * 256 + tid; i < TOTAL_MIN; i += RBLOCKS * 256)
        s += sqrtf(__uint_as_float(g_min[i]));
    ssum[tid] = s;
    __syncthreads();
    for (int off = 128; off > 0; off >>= 1) {
        if (tid < off) ssum[tid] += ssum[tid + off];
        __syncthreads();
    }
    if (tid == 0) g_part[blockIdx.x] = ssum[0];
}

__global__ void final_kernel(float* __restrict__ out) {
    __shared__ float ssum[RBLOCKS];
    int tid = threadIdx.x;
    ssum[tid] = g_part[tid];
    __syncthreads();
    for (int off = RBLOCKS / 2; off > 0; off >>= 1) {
        if (tid < off) ssum[tid] += ssum[tid + off];
        __syncthreads();
    }
    if (tid == 0) out[0] = ssum[0] / (float)BATCH;
}

extern "C" void kernel_launch(void* const* d_in, const int* in_sizes, int n_in,
                              void* d_out, int out_size) {
    const float* pred = (const float*)d_in[0];
    const float* gt   = (const float*)d_in[1];
    float* out = (float*)d_out;
    (void)in_sizes; (void)n_in; (void)out_size;

    init_kernel<<<(TOTAL_MIN + 1023) / 1024, 1024>>>();
    // grid: 2 dirs * 4 batches * 8 pred-chunks * 8 other-chunks = 512 blocks
    chamfer_main<<<2 * BATCH * PCHUNKS * OCHUNKS, TPB>>>(pred, gt);
    reduce_kernel<<<RBLOCKS, 256>>>();
    final_kernel<<<1, RBLOCKS>>>(out);
}

// round 4
// speedup vs baseline: 1.5830x; 1.5830x over previous
#include <cuda_runtime.h>
#include <math.h>

#define BATCH 4
#define NPTS  8192
#define TPB   256
#define PPT   4                         // query points per thread
#define PPB   (TPB * PPT)               // 1024 query points per block
#define PCHUNKS (NPTS / PPB)            // 8
#define CHUNK 1024                      // "other" points staged in smem
#define OCHUNKS (NPTS / CHUNK)          // 8
#define TOTAL_MIN (2 * BATCH * NPTS)    // 65536 min slots (both directions)
#define RBLOCKS 64

__device__ unsigned g_min[TOTAL_MIN];
__device__ float    g_part[RBLOCKS];

__global__ void init_kernel() {
    int i = blockIdx.x * blockDim.x + threadIdx.x;
    if (i < TOTAL_MIN) g_min[i] = 0x7f800000u;  // +inf
}

__global__ void __launch_bounds__(TPB) chamfer_main(
    const float* __restrict__ pred, const float* __restrict__ gt)
{
    // Packed scan-point data: (-2gx, -2gy, -2gz, |g|^2) -> one LDS.128 per j
    __shared__ float4 sg[CHUNK];

    int bid = blockIdx.x;
    int oc   = bid % OCHUNKS;  bid /= OCHUNKS;
    int pcid = bid % PCHUNKS;  bid /= PCHUNKS;
    int b    = bid % BATCH;    bid /= BATCH;
    int dir  = bid;  // 0: query=pred scan=gt ; 1: query=gt scan=pred

    const float* Aq = (dir == 0 ? pred : gt) + (size_t)b * 3 * NPTS;
    const float* Bs = (dir == 0 ? gt : pred) + (size_t)b * 3 * NPTS;

    // Stage + transform one chunk of the scanned cloud (coalesced [3,N] reads)
    int jbase = oc * CHUNK;
    for (int idx = threadIdx.x; idx < CHUNK; idx += TPB) {
        float gx = Bs[jbase + idx];
        float gy = Bs[NPTS + jbase + idx];
        float gz = Bs[2 * NPTS + jbase + idx];
        float cj = fmaf(gx, gx, fmaf(gy, gy, gz * gz));
        sg[idx] = make_float4(-2.0f * gx, -2.0f * gy, -2.0f * gz, cj);
    }
    __syncthreads();

    float px[PPT], py[PPT], pz[PPT], psq[PPT], mn[PPT];
    int i0 = pcid * PPB + threadIdx.x;
    #pragma unroll
    for (int p = 0; p < PPT; p++) {
        int i = i0 + p * TPB;
        px[p] = Aq[i];
        py[p] = Aq[NPTS + i];
        pz[p] = Aq[2 * NPTS + i];
        psq[p] = fmaf(px[p], px[p], fmaf(py[p], py[p], pz[p] * pz[p]));
        mn[p] = 3.0e38f;
    }

    #pragma unroll 4
    for (int j = 0; j < CHUNK; j++) {
        float4 g = sg[j];  // LDS.128 broadcast
        #pragma unroll
        for (int p = 0; p < PPT; p++) {
            // acc = |g|^2 - 2 p.g   (|p|^2 folded in after the loop)
            float acc = fmaf(pz[p], g.z, g.w);
            acc = fmaf(py[p], g.y, acc);
            acc = fmaf(px[p], g.x, acc);
            mn[p] = fminf(mn[p], acc);
        }
    }

    unsigned* gm = g_min + (size_t)dir * BATCH * NPTS + (size_t)b * NPTS;
    #pragma unroll
    for (int p = 0; p < PPT; p++) {
        float d2 = fmaxf(psq[p] + mn[p], 0.0f);  // clamp cancellation noise
        // nonnegative floats: uint order == float order -> exact deterministic min
        atomicMin(&gm[i0 + p * TPB], __float_as_uint(d2));
    }
}

__global__ void __launch_bounds__(256) reduce_kernel() {
    __shared__ float ssum[256];
    int tid = threadIdx.x;
    float s = 0.0f;
    for (int i = blockIdx.x * 256 + tid; i < TOTAL_MIN; i += RBLOCKS * 256)
        s += sqrtf(__uint_as_float(g_min[i]));
    ssum[tid] = s;
    __syncthreads();
    for (int off = 128; off > 0; off >>= 1) {
        if (tid < off) ssum[tid] += ssum[tid + off];
        __syncthreads();
    }
    if (tid == 0) g_part[blockIdx.x] = ssum[0];
}

__global__ void final_kernel(float* __restrict__ out) {
    __shared__ float ssum[RBLOCKS];
    int tid = threadIdx.x;
    ssum[tid] = g_part[tid];
    __syncthreads();
    for (int off = RBLOCKS / 2; off > 0; off >>= 1) {
        if (tid < off) ssum[tid] += ssum[tid + off];
        __syncthreads();
    }
    if (tid == 0) out[0] = ssum[0] / (float)BATCH;
}

extern "C" void kernel_launch(void* const* d_in, const int* in_sizes, int n_in,
                              void* d_out, int out_size) {
    const float* pred = (const float*)d_in[0];
    const float* gt   = (const float*)d_in[1];
    float* out = (float*)d_out;
    (void)in_sizes; (void)n_in; (void)out_size;

    init_kernel<<<(TOTAL_MIN + 1023) / 1024, 1024>>>();
    // grid: 2 dirs * 4 batches * 8 pred-chunks * 8 other-chunks = 512 blocks
    chamfer_main<<<2 * BATCH * PCHUNKS * OCHUNKS, TPB>>>(pred, gt);
    reduce_kernel<<<RBLOCKS, 256>>>();
    final_kernel<<<1, RBLOCKS>>>(out);
}